// round 1
// baseline (speedup 1.0000x reference)
#include <cuda_runtime.h>
#include <cstdint>

#define Bb 8
#define Tt 400
#define Nn 200
#define Dd 80
#define BIGNEG (-1e30f)
// 0.5 * D * log(2*pi) = 40 * 1.8378770664093453
#define HALF_D_LOG2PI 73.51508265637381f

// Scratch (no allocation allowed): emission, log_stay, log_move, each (B,T,N)
__device__ float g_em[Bb * Tt * Nn];
__device__ float g_ls[Bb * Tt * Nn];
__device__ float g_lm[Bb * Tt * Nn];

// ---------------------------------------------------------------------------
// Kernel A: one block per (b,t). Computes emission[b,t,n] for all n, and the
// transition log-probs log_stay / log_move for all n.
//   emission[b,t,n] = -(0.5 * sum_d z^2 + sum_d log(std) + 0.5*D*log(2pi)) * mask
// ---------------------------------------------------------------------------
__global__ __launch_bounds__(256) void emission_kernel(
    const float* __restrict__ mels,              // (B,T,D)
    const float* __restrict__ means,             // (B,T,N,D)
    const float* __restrict__ stds,              // (B,T,N,D)
    const float* __restrict__ tv,                // (B,T,N)
    const int*   __restrict__ inputs_len)        // (B,)
{
    const int bt  = blockIdx.x;                  // 0 .. B*T-1
    const int b   = bt / Tt;
    const int tid = threadIdx.x;
    const int w   = tid >> 5;
    const int lid = tid & 31;

    // x (mel frame) into registers: lanes cover d = lid, lid+32, lid+64
    const float* __restrict__ xr = mels + (size_t)bt * Dd;
    const float x0 = xr[lid];
    const float x1 = xr[32 + lid];
    const float x2 = (lid < 16) ? xr[64 + lid] : 0.0f;

    const int L = inputs_len[b];
    const int rowbase = bt * Nn;

    // Transition precompute: log_stay = -softplus(tv), log_move = tv - softplus(tv)
    for (int n = tid; n < Nn; n += blockDim.x) {
        float t  = tv[rowbase + n];
        float sp = __logf(1.0f + __expf(t));
        g_ls[rowbase + n] = -sp;
        g_lm[rowbase + n] = t - sp;
    }

    // Emission: warp w handles states n = w, w+8, ...
    for (int n = w; n < Nn; n += 8) {
        const size_t base = (size_t)(rowbase + n) * Dd;
        const float* __restrict__ mp = means + base;
        const float* __restrict__ sp = stds  + base;

        float m0 = mp[lid],      s0 = sp[lid];
        float m1 = mp[32 + lid], s1 = sp[32 + lid];
        float m2 = 0.0f, s2 = 1.0f;
        if (lid < 16) { m2 = mp[64 + lid]; s2 = sp[64 + lid]; }

        float z0 = __fdividef(x0 - m0, s0);
        float z1 = __fdividef(x1 - m1, s1);
        float z2 = (lid < 16) ? __fdividef(x2 - m2, s2) : 0.0f;

        float acc = z0 * z0 + z1 * z1 + z2 * z2;   // sum z^2 (partial)
        float p   = s0 * s1 * s2;                  // product of stds (partial)
        // combined value: 0.5*sum z^2 + sum log(std)
        float v = 0.5f * acc + __logf(p);

        #pragma unroll
        for (int off = 16; off; off >>= 1)
            v += __shfl_xor_sync(0xffffffffu, v, off);

        if (lid == 0) {
            float em = -(v + HALF_D_LOG2PI);
            g_em[rowbase + n] = (n < L) ? em : 0.0f;
        }
    }
}

// ---------------------------------------------------------------------------
// Kernel B: forward scan, one warp per batch element. Unnormalized alphas.
// Each lane owns 7 consecutive states in registers. Output:
//   out[b] = A_lastT[L-1] + log_stay[b, lastT, L-1]
// ---------------------------------------------------------------------------
#define LOADROW(t_, e_, l_, m_)                                            \
    do {                                                                   \
        int r_ = base + (t_) * Nn + n0;                                    \
        _Pragma("unroll")                                                  \
        for (int j_ = 0; j_ < 7; j_++) {                                   \
            int n_ = n0 + j_;                                              \
            if (n_ < Nn) {                                                 \
                e_[j_] = __ldg(&g_em[r_ + j_]);                            \
                l_[j_] = __ldg(&g_ls[r_ + j_]);                            \
                m_[j_] = __ldg(&g_lm[r_ + j_]);                            \
            } else {                                                       \
                e_[j_] = 0.0f; l_[j_] = 0.0f; m_[j_] = 0.0f;               \
            }                                                              \
        }                                                                  \
    } while (0)

__global__ __launch_bounds__(32) void scan_kernel(
    const int* __restrict__ inputs_len,
    const int* __restrict__ mel_lens,
    float* __restrict__ out)
{
    const int b    = blockIdx.x;
    const int lane = threadIdx.x;
    const int L     = inputs_len[b];
    const int lastT = mel_lens[b] - 1;
    const int n0    = lane * 7;
    const int base  = b * Tt * Nn;

    float A[7];
    #pragma unroll
    for (int j = 0; j < 7; j++) {
        int n = n0 + j;
        A[j] = (n == 0) ? g_em[base] : BIGNEG;   // t=0: priors + emission
    }

    float em_n[7], ls_n[7], lm_n[7];
    float em_c[7], ls_c[7], lm_c[7];

    if (lastT >= 1) LOADROW(1, em_n, ls_n, lm_n);

    for (int t = 1; t <= lastT; t++) {
        #pragma unroll
        for (int j = 0; j < 7; j++) {
            em_c[j] = em_n[j]; ls_c[j] = ls_n[j]; lm_c[j] = lm_n[j];
        }
        if (t + 1 <= lastT) LOADROW(t + 1, em_n, ls_n, lm_n);

        float prev = __shfl_up_sync(0xffffffffu, A[6], 1);
        if (lane == 0) prev = BIGNEG;

        float carry = prev;                      // old A[n-1]
        #pragma unroll
        for (int j = 0; j < 7; j++) {
            int n = n0 + j;
            float oldA = A[j];
            float stay = oldA  + ls_c[j];
            float mv   = carry + lm_c[j];
            float mx = fmaxf(stay, mv);
            float mn = fminf(stay, mv);
            float r  = mx + __logf(1.0f + __expf(mn - mx));   // logaddexp
            A[j] = (n < L) ? (em_c[j] + r) : BIGNEG;
            carry = oldA;
        }
    }

    const int nl = L - 1;
    if (lane == nl / 7) {
        const int jj = nl - (nl / 7) * 7;
        float av = A[0];
        #pragma unroll
        for (int j = 1; j < 7; j++)
            if (jj == j) av = A[j];
        float lsl = g_ls[base + lastT * Nn + nl];
        out[b] = av + lsl;
    }
}

// ---------------------------------------------------------------------------
// Launch
// Inputs (metadata order): mels, means, stds, transition_vector,
//                          inputs_len(int32), mel_lens(int32)
// Output: (B,) float32
// ---------------------------------------------------------------------------
extern "C" void kernel_launch(void* const* d_in, const int* in_sizes, int n_in,
                              void* d_out, int out_size)
{
    const float* mels  = (const float*)d_in[0];
    const float* means = (const float*)d_in[1];
    const float* stds  = (const float*)d_in[2];
    const float* tv    = (const float*)d_in[3];
    const int*   ilen  = (const int*)d_in[4];
    const int*   mlen  = (const int*)d_in[5];
    float* out = (float*)d_out;

    emission_kernel<<<Bb * Tt, 256>>>(mels, means, stds, tv, ilen);
    scan_kernel<<<Bb, 32>>>(ilen, mlen, out);
}

// round 2
// speedup vs baseline: 1.2734x; 1.2734x over previous
#include <cuda_runtime.h>
#include <cstdint>

#define Bb 8
#define Tt 400
#define Nn 200
#define Dd 80
#define BIGNEG (-1e30f)
// 0.5 * D * log(2*pi) = 40 * 1.8378770664093453
#define HALF_D_LOG2PI 73.51508265637381f

// Scratch (no allocation allowed): emission, log_stay, log_move, each (B,T,N)
__device__ float g_em[Bb * Tt * Nn];
__device__ float g_ls[Bb * Tt * Nn];
__device__ float g_lm[Bb * Tt * Nn];

// ---------------------------------------------------------------------------
// Kernel A: one block per (b,t). Computes emission[b,t,n] for all n, and the
// transition log-probs log_stay / log_move for all n.
//   emission[b,t,n] = -(0.5 * sum_d z^2 + sum_d log(std) + 0.5*D*log(2pi)) * mask
// ---------------------------------------------------------------------------
__global__ __launch_bounds__(256) void emission_kernel(
    const float* __restrict__ mels,              // (B,T,D)
    const float* __restrict__ means,             // (B,T,N,D)
    const float* __restrict__ stds,              // (B,T,N,D)
    const float* __restrict__ tv,                // (B,T,N)
    const int*   __restrict__ inputs_len)        // (B,)
{
    const int bt  = blockIdx.x;                  // 0 .. B*T-1
    const int b   = bt / Tt;
    const int tid = threadIdx.x;
    const int w   = tid >> 5;
    const int lid = tid & 31;

    // x (mel frame) into registers: lanes cover d = lid, lid+32, lid+64
    const float* __restrict__ xr = mels + (size_t)bt * Dd;
    const float x0 = xr[lid];
    const float x1 = xr[32 + lid];
    const float x2 = (lid < 16) ? xr[64 + lid] : 0.0f;

    const int L = inputs_len[b];
    const int rowbase = bt * Nn;

    // Transition precompute: log_stay = -softplus(tv), log_move = tv - softplus(tv)
    for (int n = tid; n < Nn; n += blockDim.x) {
        float t  = tv[rowbase + n];
        float sp = __logf(1.0f + __expf(t));
        g_ls[rowbase + n] = -sp;
        g_lm[rowbase + n] = t - sp;
    }

    // Emission: warp w handles states n = w, w+8, ...
    for (int n = w; n < Nn; n += 8) {
        const size_t base = (size_t)(rowbase + n) * Dd;
        const float* __restrict__ mp = means + base;
        const float* __restrict__ sp = stds  + base;

        float m0 = mp[lid],      s0 = sp[lid];
        float m1 = mp[32 + lid], s1 = sp[32 + lid];
        float m2 = 0.0f, s2 = 1.0f;
        if (lid < 16) { m2 = mp[64 + lid]; s2 = sp[64 + lid]; }

        float z0 = __fdividef(x0 - m0, s0);
        float z1 = __fdividef(x1 - m1, s1);
        float z2 = (lid < 16) ? __fdividef(x2 - m2, s2) : 0.0f;

        float acc = z0 * z0 + z1 * z1 + z2 * z2;   // sum z^2 (partial)
        float p   = s0 * s1 * s2;                  // product of stds (partial)
        // combined value: 0.5*sum z^2 + sum log(std)
        float v = 0.5f * acc + __logf(p);

        #pragma unroll
        for (int off = 16; off; off >>= 1)
            v += __shfl_xor_sync(0xffffffffu, v, off);

        if (lid == 0) {
            float em = -(v + HALF_D_LOG2PI);
            g_em[rowbase + n] = (n < L) ? em : 0.0f;
        }
    }
}

// ---------------------------------------------------------------------------
// Kernel B: forward scan, one BLOCK per batch element, one thread per state.
// Unnormalized alphas carried in registers; neighbor value A[n-1] exchanged
// through a double-buffered shared array (one __syncthreads per step).
// Depth-2 register prefetch hides L2 latency of the (em, ls, lm) rows.
// Output: out[b] = A_lastT[L-1] + log_stay[b, lastT, L-1]
// ---------------------------------------------------------------------------
__global__ __launch_bounds__(224) void scan_kernel(
    const int* __restrict__ inputs_len,
    const int* __restrict__ mel_lens,
    float* __restrict__ out)
{
    const int b = blockIdx.x;
    const int n = threadIdx.x;                   // state index (< Nn active)
    const bool act = (n < Nn);

    const int L     = inputs_len[b];
    const int lastT = mel_lens[b] - 1;
    const int base  = b * Tt * Nn;

    __shared__ float Abuf[2][Nn + 1];            // slot 0 = virtual state -1

    // t = 0 init: A = priors + emission (prior finite only at state 0)
    float A = BIGNEG;
    if (act) A = (n == 0) ? g_em[base] : BIGNEG;
    if (n == 0) { Abuf[0][0] = BIGNEG; Abuf[1][0] = BIGNEG; }
    if (act) Abuf[0][n + 1] = A;

    // depth-2 prefetch of rows t=1, t=2 (clamped to lastT; redundant loads ok)
    float em1 = 0.f, ls1 = 0.f, lm1 = 0.f;
    float em2 = 0.f, ls2 = 0.f, lm2 = 0.f;
    if (act) {
        int t1 = (1 < lastT) ? 1 : lastT;
        int t2 = (2 < lastT) ? 2 : lastT;
        if (t1 < 0) t1 = 0;
        if (t2 < 0) t2 = 0;
        int r1 = base + t1 * Nn + n;
        int r2 = base + t2 * Nn + n;
        em1 = __ldg(&g_em[r1]); ls1 = __ldg(&g_ls[r1]); lm1 = __ldg(&g_lm[r1]);
        em2 = __ldg(&g_em[r2]); ls2 = __ldg(&g_ls[r2]); lm2 = __ldg(&g_lm[r2]);
    }
    __syncthreads();

    int buf = 0;
    for (int t = 1; t <= lastT; t++) {
        // rotate prefetch buffers; issue loads for t+2
        const float em = em1, ls = ls1, lm = lm1;
        em1 = em2; ls1 = ls2; lm1 = lm2;
        if (act) {
            int tn = (t + 2 <= lastT) ? (t + 2) : lastT;
            int r  = base + tn * Nn + n;
            em2 = __ldg(&g_em[r]); ls2 = __ldg(&g_ls[r]); lm2 = __ldg(&g_lm[r]);
        }

        if (act) {
            float prev = Abuf[buf][n];           // A[n-1] from previous step
            float stay = A + ls;
            float mv   = prev + lm;
            float mx = fmaxf(stay, mv);
            float mn = fminf(stay, mv);
            float r  = mx + __logf(1.0f + __expf(mn - mx));   // logaddexp
            A = (n < L) ? (em + r) : BIGNEG;
            Abuf[buf ^ 1][n + 1] = A;
        }
        __syncthreads();
        buf ^= 1;
    }

    if (act && n == (L - 1)) {
        out[b] = A + g_ls[base + lastT * Nn + n];
    }
}

// ---------------------------------------------------------------------------
// Launch
// Inputs (metadata order): mels, means, stds, transition_vector,
//                          inputs_len(int32), mel_lens(int32)
// Output: (B,) float32
// ---------------------------------------------------------------------------
extern "C" void kernel_launch(void* const* d_in, const int* in_sizes, int n_in,
                              void* d_out, int out_size)
{
    const float* mels  = (const float*)d_in[0];
    const float* means = (const float*)d_in[1];
    const float* stds  = (const float*)d_in[2];
    const float* tv    = (const float*)d_in[3];
    const int*   ilen  = (const int*)d_in[4];
    const int*   mlen  = (const int*)d_in[5];
    float* out = (float*)d_out;

    emission_kernel<<<Bb * Tt, 256>>>(mels, means, stds, tv, ilen);
    scan_kernel<<<Bb, 224>>>(ilen, mlen, out);
}

// round 3
// speedup vs baseline: 1.4405x; 1.1312x over previous
#include <cuda_runtime.h>
#include <cstdint>

#define Bb 8
#define Tt 400
#define Nn 200
#define Dd 80
#define BIGNEG (-1e30f)
// 0.5 * D * log(2*pi) = 40 * 1.8378770664093453
#define HALF_D_LOG2PI 73.51508265637381f
#define CHUNK 8
#define NPAD 224   // padded state dim so lane 31 (n up to 223) stays in-bounds

// Scratch (no allocation allowed): emission, log_stay, log_move, each (B,T,N)
__device__ float g_em[Bb * Tt * Nn];
__device__ float g_ls[Bb * Tt * Nn];
__device__ float g_lm[Bb * Tt * Nn];

// ---------------------------------------------------------------------------
// Kernel A: one block per (b,t). Emission for states n < L, transitions for
// all n. Blocks with t >= mel_lens[b] exit immediately (scanner never reads
// those rows) — saves ~25% HBM traffic; skipping n >= L saves ~25% more.
// ---------------------------------------------------------------------------
__global__ __launch_bounds__(256) void emission_kernel(
    const float* __restrict__ mels,              // (B,T,D)
    const float* __restrict__ means,             // (B,T,N,D)
    const float* __restrict__ stds,              // (B,T,N,D)
    const float* __restrict__ tv,                // (B,T,N)
    const int*   __restrict__ inputs_len,        // (B,)
    const int*   __restrict__ mel_lens)          // (B,)
{
    const int bt  = blockIdx.x;                  // 0 .. B*T-1
    const int b   = bt / Tt;
    const int t   = bt - b * Tt;
    if (t >= mel_lens[b]) return;                // row never consumed

    const int tid = threadIdx.x;
    const int w   = tid >> 5;
    const int lid = tid & 31;

    // x (mel frame) into registers: lanes cover d = lid, lid+32, lid+64
    const float* __restrict__ xr = mels + (size_t)bt * Dd;
    const float x0 = xr[lid];
    const float x1 = xr[32 + lid];
    const float x2 = (lid < 16) ? xr[64 + lid] : 0.0f;

    const int L = inputs_len[b];
    const int rowbase = bt * Nn;

    // Transition precompute: log_stay = -softplus(tv), log_move = tv - softplus(tv)
    for (int n = tid; n < Nn; n += blockDim.x) {
        float tvv = tv[rowbase + n];
        float sp  = __logf(1.0f + __expf(tvv));
        g_ls[rowbase + n] = -sp;
        g_lm[rowbase + n] = tvv - sp;
    }

    // Emission: warp w handles states n = w, w+8, ... (< L only)
    for (int n = w; n < L; n += 8) {
        const size_t base = (size_t)(rowbase + n) * Dd;
        const float* __restrict__ mp = means + base;
        const float* __restrict__ sp = stds  + base;

        float m0 = mp[lid],      s0 = sp[lid];
        float m1 = mp[32 + lid], s1 = sp[32 + lid];
        float m2 = 0.0f, s2 = 1.0f;
        if (lid < 16) { m2 = mp[64 + lid]; s2 = sp[64 + lid]; }

        float z0 = __fdividef(x0 - m0, s0);
        float z1 = __fdividef(x1 - m1, s1);
        float z2 = (lid < 16) ? __fdividef(x2 - m2, s2) : 0.0f;

        float acc = z0 * z0 + z1 * z1 + z2 * z2;   // sum z^2 (partial)
        float p   = s0 * s1 * s2;                  // product of stds (partial)
        float v = 0.5f * acc + __logf(p);          // 0.5*sum z^2 + sum log(std)

        #pragma unroll
        for (int off = 16; off; off >>= 1)
            v += __shfl_xor_sync(0xffffffffu, v, off);

        if (lid == 0)
            g_em[rowbase + n] = -(v + HALF_D_LOG2PI);
    }
}

// ---------------------------------------------------------------------------
// Kernel B: warp-specialized scan. One block per batch, 256 threads.
//   warps 1-7: stage (em, ls, lm) rows in CHUNK-step chunks into a
//              double-buffered shared ring (bulk coalesced L2 loads)
//   warp 0:    sequential recurrence, 7 states per lane in registers,
//              one shfl per step, ZERO per-step barriers (one per chunk)
// Output: out[b] = A_lastT[L-1] + log_move[b, lastT, L-1]
// ---------------------------------------------------------------------------
__global__ __launch_bounds__(256) void scan_kernel(
    const int* __restrict__ inputs_len,
    const int* __restrict__ mel_lens,
    float* __restrict__ out)
{
    const int b    = blockIdx.x;
    const int tid  = threadIdx.x;
    const int wid  = tid >> 5;
    const int lane = tid & 31;

    const int L     = inputs_len[b];
    const int lastT = mel_lens[b] - 1;
    const int base  = b * Tt * Nn;

    __shared__ float buf[2][CHUNK][3][NPAD];     // 43008 B

    const int nsteps  = lastT;                   // steps t = 1 .. lastT
    const int nchunks = (nsteps + CHUNK - 1) / CHUNK;

    // ---- scanner state init (t = 0) ----
    const int n0 = lane * 7;
    float A[7];
    bool  msk[7];
    #pragma unroll
    for (int j = 0; j < 7; j++) {
        msk[j] = (n0 + j) < L;
        A[j] = BIGNEG;
    }
    if (wid == 0 && lane == 0) A[0] = g_em[base];   // priors: state 0 only

    // ---- prologue: loaders fill chunk 0 ----
    if (wid > 0) {
        const int ltid = tid - 32;               // 0 .. 223
        int t0  = 1;
        int cnt = (CHUNK < nsteps) ? CHUNK : nsteps;
        for (int idx = ltid; idx < cnt * Nn; idx += 224) {
            int s = idx / Nn, n = idx - s * Nn;
            int g = base + (t0 + s) * Nn + n;
            buf[0][s][0][n] = __ldg(&g_em[g]);
            buf[0][s][1][n] = __ldg(&g_ls[g]);
            buf[0][s][2][n] = __ldg(&g_lm[g]);
        }
    }
    __syncthreads();

    for (int c = 0; c < nchunks; c++) {
        if (wid > 0) {
            // load chunk c+1 into the other buffer
            if (c + 1 < nchunks) {
                const int ltid = tid - 32;
                int t0  = 1 + (c + 1) * CHUNK;
                int rem = nsteps - (c + 1) * CHUNK;
                int cnt = (CHUNK < rem) ? CHUNK : rem;
                float (*dst)[3][NPAD] = buf[(c + 1) & 1];
                for (int idx = ltid; idx < cnt * Nn; idx += 224) {
                    int s = idx / Nn, n = idx - s * Nn;
                    int g = base + (t0 + s) * Nn + n;
                    dst[s][0][n] = __ldg(&g_em[g]);
                    dst[s][1][n] = __ldg(&g_ls[g]);
                    dst[s][2][n] = __ldg(&g_lm[g]);
                }
            }
        } else {
            // scan chunk c
            int rem = nsteps - c * CHUNK;
            int cnt = (CHUNK < rem) ? CHUNK : rem;
            float (*src)[3][NPAD] = buf[c & 1];
            for (int s = 0; s < cnt; s++) {
                float prev = __shfl_up_sync(0xffffffffu, A[6], 1);
                if (lane == 0) prev = BIGNEG;
                float carry = prev;              // old A[n-1]
                #pragma unroll
                for (int j = 0; j < 7; j++) {
                    float em = src[s][0][n0 + j];
                    float ls = src[s][1][n0 + j];
                    float lm = src[s][2][n0 + j];
                    float oldA = A[j];
                    float stay = oldA  + ls;
                    float mv   = carry + lm;
                    float mx = fmaxf(stay, mv);
                    float mn = fminf(stay, mv);
                    float r  = mx + __logf(1.0f + __expf(mn - mx));
                    A[j] = msk[j] ? (em + r) : BIGNEG;
                    carry = oldA;
                }
            }
        }
        __syncthreads();
    }

    // ---- epilogue: absorption factor uses log_move at (lastT, L-1) ----
    if (wid == 0) {
        const int nl = L - 1;
        if (lane == nl / 7) {
            const int jj = nl - (nl / 7) * 7;
            float av = A[0];
            #pragma unroll
            for (int j = 1; j < 7; j++)
                if (jj == j) av = A[j];
            out[b] = av + g_lm[base + lastT * Nn + nl];
        }
    }
}

// ---------------------------------------------------------------------------
// Launch
// Inputs (metadata order): mels, means, stds, transition_vector,
//                          inputs_len(int32), mel_lens(int32)
// Output: (B,) float32
// ---------------------------------------------------------------------------
extern "C" void kernel_launch(void* const* d_in, const int* in_sizes, int n_in,
                              void* d_out, int out_size)
{
    const float* mels  = (const float*)d_in[0];
    const float* means = (const float*)d_in[1];
    const float* stds  = (const float*)d_in[2];
    const float* tv    = (const float*)d_in[3];
    const int*   ilen  = (const int*)d_in[4];
    const int*   mlen  = (const int*)d_in[5];
    float* out = (float*)d_out;

    emission_kernel<<<Bb * Tt, 256>>>(mels, means, stds, tv, ilen, mlen);
    scan_kernel<<<Bb, 256>>>(ilen, mlen, out);
}